// round 1
// baseline (speedup 1.0000x reference)
#include <cuda_runtime.h>

#define D   4096
#define BSR 4096          // B*S rows
#define SEQ 1024
#define NH  32
#define HD  128
#define LR  16

// ---------------- scratch (static device globals; no runtime alloc) -------
__device__ float g_WqE[(size_t)D * D];
__device__ float g_WvE[(size_t)D * D];
__device__ float g_Q[(size_t)BSR * D];
__device__ float g_K[(size_t)BSR * D];
__device__ float g_V[(size_t)BSR * D];
__device__ float g_O[(size_t)BSR * D];

// ---------------- LoRA weight merge: out = w + 2 * (b @ a) ----------------
__global__ void merge_kernel(const float* __restrict__ w,
                             const float* __restrict__ a,
                             const float* __restrict__ b,
                             float* __restrict__ o) {
    int idx = blockIdx.x * 256 + threadIdx.x;      // over D*D
    int n = idx >> 12;
    int k = idx & (D - 1);
    float acc = w[idx];
#pragma unroll
    for (int r = 0; r < LR; r++)
        acc += 2.0f * __ldg(&b[n * LR + r]) * __ldg(&a[r * D + k]);
    o[idx] = acc;
}

// ---------------- SGEMM (NT): C[m,n] = dot(A[m,:], W[n,:]) ----------------
// A: [4096,4096] row-major, W: [4096,4096] row-major, C: [4096,4096].
// 128x128 block tile, BK=16, 256 threads, 8x8 register micro-tile.
__global__ void __launch_bounds__(256) sgemm_nt(const float* __restrict__ A,
                                                const float* __restrict__ W,
                                                float* __restrict__ C) {
    __shared__ float As[16][132];
    __shared__ float Ws[16][132];

    const int tid = threadIdx.x;
    const int bm = blockIdx.y * 128;
    const int bn = blockIdx.x * 128;
    const int tx = tid & 15;        // 0..15 -> n sub-tile
    const int ty = tid >> 4;        // 0..15 -> m sub-tile
    const int lr = tid >> 2;        // 0..63 loader row
    const int lc = tid & 3;         // 0..3  loader float4 col

    float acc[8][8];
#pragma unroll
    for (int i = 0; i < 8; i++)
#pragma unroll
        for (int j = 0; j < 8; j++) acc[i][j] = 0.0f;

    const float* Ap = A + (size_t)(bm + lr) * D + lc * 4;
    const float* Wp = W + (size_t)(bn + lr) * D + lc * 4;

    for (int kt = 0; kt < D; kt += 16) {
#pragma unroll
        for (int h2 = 0; h2 < 2; h2++) {
            float4 va = *(const float4*)(Ap + (size_t)h2 * 64 * D + kt);
            int row = lr + h2 * 64;
            As[lc * 4 + 0][row] = va.x;
            As[lc * 4 + 1][row] = va.y;
            As[lc * 4 + 2][row] = va.z;
            As[lc * 4 + 3][row] = va.w;
            float4 vw = *(const float4*)(Wp + (size_t)h2 * 64 * D + kt);
            Ws[lc * 4 + 0][row] = vw.x;
            Ws[lc * 4 + 1][row] = vw.y;
            Ws[lc * 4 + 2][row] = vw.z;
            Ws[lc * 4 + 3][row] = vw.w;
        }
        __syncthreads();
#pragma unroll
        for (int k = 0; k < 16; k++) {
            float a[8], bv[8];
            *(float4*)&a[0]  = *(const float4*)&As[k][ty * 8];
            *(float4*)&a[4]  = *(const float4*)&As[k][ty * 8 + 4];
            *(float4*)&bv[0] = *(const float4*)&Ws[k][tx * 8];
            *(float4*)&bv[4] = *(const float4*)&Ws[k][tx * 8 + 4];
#pragma unroll
            for (int i = 0; i < 8; i++)
#pragma unroll
                for (int j = 0; j < 8; j++) acc[i][j] += a[i] * bv[j];
        }
        __syncthreads();
    }

#pragma unroll
    for (int i = 0; i < 8; i++) {
        float* Cp = C + (size_t)(bm + ty * 8 + i) * D + bn + tx * 8;
        *(float4*)Cp       = make_float4(acc[i][0], acc[i][1], acc[i][2], acc[i][3]);
        *(float4*)(Cp + 4) = make_float4(acc[i][4], acc[i][5], acc[i][6], acc[i][7]);
    }
}

// ---------------- RoPE on g_Q and g_K (in place) ---------------------------
__global__ void rope_kernel(const float* __restrict__ fc,
                            const float* __restrict__ fs) {
    int p = blockIdx.x * 256 + threadIdx.x;   // pair index over BSR * (D/2)
    int row = p >> 11;                         // D/2 = 2048 pairs per row
    int cp  = p & 2047;
    int i   = cp & 63;                         // HD/2 = 64
    int s   = row & (SEQ - 1);
    float c  = fc[s * 64 + i];
    float sn = fs[s * 64 + i];
    size_t base = (size_t)row * D + cp * 2;

    float2 q = *(float2*)&g_Q[base];
    *(float2*)&g_Q[base] = make_float2(q.x * c - q.y * sn, q.x * sn + q.y * c);
    float2 k = *(float2*)&g_K[base];
    *(float2*)&g_K[base] = make_float2(k.x * c - k.y * sn, k.x * sn + k.y * c);
}

// ---------------- flash attention (fp32, causal) ---------------------------
// grid: (S/128, H, B). 256 threads. BM=128 q rows, BN=64 k rows.
// thread (tx=tid&7, ty=tid>>3): owns S rows ty*4+rr, S cols tx+8*cc,
// O cols tx+8*cc (cc 0..15).
#define ATTN_SMEM ((128 * 132 + 64 * 132 + 64 * 132 + 128 * 68) * 4)

__global__ void __launch_bounds__(256) attn_kernel() {
    extern __shared__ float sm[];
    float* Qs = sm;                   // [128][132]
    float* Ks = sm + 128 * 132;       // [64][132]
    float* Vs = Ks + 64 * 132;        // [64][132]
    float* Ps = Vs + 64 * 132;        // [128][68]

    const int b = blockIdx.z, h = blockIdx.y, qt = blockIdx.x;
    const int q0 = qt * 128;
    const int tid = threadIdx.x;
    const int tx = tid & 7, ty = tid >> 3;
    const float SCALE = 0.08838834764831845f;   // 1/sqrt(128)

    const float* Qg = g_Q + ((size_t)(b * SEQ + q0)) * D + h * HD;
    const float* Kg = g_K + ((size_t)(b * SEQ)) * D + h * HD;
    const float* Vg = g_V + ((size_t)(b * SEQ)) * D + h * HD;

    for (int l = tid; l < 128 * 32; l += 256) {
        int row = l >> 5, c4 = l & 31;
        *(float4*)&Qs[row * 132 + c4 * 4] = *(const float4*)&Qg[(size_t)row * D + c4 * 4];
    }

    float o[4][16];
    float m[4], lsum[4];
#pragma unroll
    for (int r = 0; r < 4; r++) {
        m[r] = -1e30f; lsum[r] = 0.0f;
#pragma unroll
        for (int c = 0; c < 16; c++) o[r][c] = 0.0f;
    }

    const int ktiles = 2 * qt + 2;
    for (int kt = 0; kt < ktiles; kt++) {
        const int k0 = kt * 64;
        __syncthreads();
        for (int l = tid; l < 64 * 32; l += 256) {
            int row = l >> 5, c4 = l & 31;
            *(float4*)&Ks[row * 132 + c4 * 4] = *(const float4*)&Kg[(size_t)(k0 + row) * D + c4 * 4];
            *(float4*)&Vs[row * 132 + c4 * 4] = *(const float4*)&Vg[(size_t)(k0 + row) * D + c4 * 4];
        }
        __syncthreads();

        // --- S = Q K^T tile ---
        float sc[4][8];
#pragma unroll
        for (int r = 0; r < 4; r++)
#pragma unroll
            for (int c = 0; c < 8; c++) sc[r][c] = 0.0f;

#pragma unroll 4
        for (int kk4 = 0; kk4 < 32; kk4++) {
            float4 a4[4], b4[8];
#pragma unroll
            for (int r = 0; r < 4; r++)
                a4[r] = *(const float4*)&Qs[(ty * 4 + r) * 132 + kk4 * 4];
#pragma unroll
            for (int c = 0; c < 8; c++)
                b4[c] = *(const float4*)&Ks[(tx + 8 * c) * 132 + kk4 * 4];
#pragma unroll
            for (int r = 0; r < 4; r++)
#pragma unroll
                for (int c = 0; c < 8; c++)
                    sc[r][c] += a4[r].x * b4[c].x + a4[r].y * b4[c].y +
                                a4[r].z * b4[c].z + a4[r].w * b4[c].w;
        }

        // --- scale + causal mask ---
        const bool need_mask = (k0 + 63 > q0);
#pragma unroll
        for (int r = 0; r < 4; r++) {
            int ig = q0 + ty * 4 + r;
#pragma unroll
            for (int c = 0; c < 8; c++) {
                float v = sc[r][c] * SCALE;
                if (need_mask && (k0 + tx + 8 * c > ig)) v = -1e30f;
                sc[r][c] = v;
            }
        }

        // --- online softmax ---
#pragma unroll
        for (int r = 0; r < 4; r++) {
            float mx = sc[r][0];
#pragma unroll
            for (int c = 1; c < 8; c++) mx = fmaxf(mx, sc[r][c]);
            mx = fmaxf(mx, __shfl_xor_sync(0xffffffffu, mx, 1));
            mx = fmaxf(mx, __shfl_xor_sync(0xffffffffu, mx, 2));
            mx = fmaxf(mx, __shfl_xor_sync(0xffffffffu, mx, 4));
            float mnew = fmaxf(m[r], mx);
            float alpha = __expf(m[r] - mnew);
            float s = 0.0f;
#pragma unroll
            for (int c = 0; c < 8; c++) {
                float p = __expf(sc[r][c] - mnew);
                sc[r][c] = p;
                s += p;
            }
            s += __shfl_xor_sync(0xffffffffu, s, 1);
            s += __shfl_xor_sync(0xffffffffu, s, 2);
            s += __shfl_xor_sync(0xffffffffu, s, 4);
            lsum[r] = lsum[r] * alpha + s;
            m[r] = mnew;
#pragma unroll
            for (int c = 0; c < 16; c++) o[r][c] *= alpha;
        }

        // --- publish P ---
#pragma unroll
        for (int r = 0; r < 4; r++)
#pragma unroll
            for (int c = 0; c < 8; c++)
                Ps[(ty * 4 + r) * 68 + tx + 8 * c] = sc[r][c];
        __syncthreads();

        // --- O += P V ---
#pragma unroll 2
        for (int j = 0; j < 64; j++) {
            float p[4];
#pragma unroll
            for (int r = 0; r < 4; r++) p[r] = Ps[(ty * 4 + r) * 68 + j];
#pragma unroll
            for (int c = 0; c < 16; c++) {
                float v = Vs[j * 132 + tx + 8 * c];
#pragma unroll
                for (int r = 0; r < 4; r++) o[r][c] += p[r] * v;
            }
        }
    }

    // --- epilogue: normalize + write ---
#pragma unroll
    for (int r = 0; r < 4; r++) {
        float inv = 1.0f / lsum[r];
        size_t rowoff = ((size_t)(b * SEQ + q0 + ty * 4 + r)) * D + h * HD;
#pragma unroll
        for (int c = 0; c < 16; c++)
            g_O[rowoff + tx + 8 * c] = o[r][c] * inv;
    }
}

// ---------------- launcher -------------------------------------------------
extern "C" void kernel_launch(void* const* d_in, const int* in_sizes, int n_in,
                              void* d_out, int out_size) {
    const float* x    = (const float*)d_in[0];
    const float* wq_w = (const float*)d_in[1];
    const float* wq_a = (const float*)d_in[2];
    const float* wq_b = (const float*)d_in[3];
    const float* wk_w = (const float*)d_in[4];
    const float* wv_w = (const float*)d_in[5];
    const float* wv_a = (const float*)d_in[6];
    const float* wv_b = (const float*)d_in[7];
    const float* wo_w = (const float*)d_in[8];
    const float* fc   = (const float*)d_in[9];
    const float* fs   = (const float*)d_in[10];
    // d_in[11] = mask (implemented analytically), d_in[12] = start_pos (0)
    float* out = (float*)d_out;

    float *WqE, *WvE, *Q, *K, *V, *O;
    cudaGetSymbolAddress((void**)&WqE, g_WqE);
    cudaGetSymbolAddress((void**)&WvE, g_WvE);
    cudaGetSymbolAddress((void**)&Q,   g_Q);
    cudaGetSymbolAddress((void**)&K,   g_K);
    cudaGetSymbolAddress((void**)&V,   g_V);
    cudaGetSymbolAddress((void**)&O,   g_O);

    cudaFuncSetAttribute(attn_kernel,
                         cudaFuncAttributeMaxDynamicSharedMemorySize, ATTN_SMEM);

    // 1) fold LoRA into weights
    merge_kernel<<<(D * D) / 256, 256>>>(wq_w, wq_a, wq_b, WqE);
    merge_kernel<<<(D * D) / 256, 256>>>(wv_w, wv_a, wv_b, WvE);

    // 2) projections
    dim3 g(32, 32);
    sgemm_nt<<<g, 256>>>(x, WqE, Q);
    sgemm_nt<<<g, 256>>>(x, wk_w, K);
    sgemm_nt<<<g, 256>>>(x, WvE, V);

    // 3) RoPE on Q, K
    rope_kernel<<<(BSR * (D / 2)) / 256, 256>>>(fc, fs);

    // 4) causal flash attention -> g_O in [B,S,H*HD] layout
    attn_kernel<<<dim3(SEQ / 128, NH, 4), 256, ATTN_SMEM>>>();

    // 5) output projection
    sgemm_nt<<<g, 256>>>(O, wo_w, out);
}

// round 3
// speedup vs baseline: 2.0657x; 2.0657x over previous
#include <cuda_runtime.h>
#include <cuda_bf16.h>
#include <cstdint>

#define D   4096
#define BSR 4096
#define SEQ 1024
#define NH  32
#define HD  128
#define LR  16

// ------------------------- device scratch ---------------------------------
__device__ __nv_bfloat16 g_xh[(size_t)BSR * D], g_xl[(size_t)BSR * D];
__device__ __nv_bfloat16 g_Wqh[(size_t)D * D], g_Wql[(size_t)D * D];
__device__ __nv_bfloat16 g_Wkh[(size_t)D * D], g_Wkl[(size_t)D * D];
__device__ __nv_bfloat16 g_Wvh[(size_t)D * D], g_Wvl[(size_t)D * D];
__device__ __nv_bfloat16 g_Woh[(size_t)D * D], g_Wol[(size_t)D * D];
__device__ __nv_bfloat16 g_Oh[(size_t)BSR * D], g_Ol[(size_t)BSR * D];
__device__ float g_Q[(size_t)BSR * D], g_K[(size_t)BSR * D];
__device__ float g_V[(size_t)BSR * D], g_O[(size_t)BSR * D];

// ------------------------- PTX helpers (base-target only) ------------------
__device__ __forceinline__ uint32_t smem_to_u32(const void* p) {
    uint32_t a;
    asm("{ .reg .u64 t; cvta.to.shared.u64 t, %1; cvt.u32.u64 %0, t; }"
        : "=r"(a) : "l"(p));
    return a;
}
#define CP16(dst, src) \
    asm volatile("cp.async.cg.shared.global [%0], [%1], 16;" \
                 :: "r"(dst), "l"(src))
#define CP_COMMIT() asm volatile("cp.async.commit_group;" ::: "memory")
#define CP_WAIT1()  asm volatile("cp.async.wait_group 1;" ::: "memory")
#define CP_WAIT0()  asm volatile("cp.async.wait_group 0;" ::: "memory")

#define LDSM4(r0, r1, r2, r3, addr) \
    asm volatile("ldmatrix.sync.aligned.m8n8.x4.shared.b16 {%0,%1,%2,%3}, [%4];" \
                 : "=r"(r0), "=r"(r1), "=r"(r2), "=r"(r3) : "r"(addr))
#define LDSM2(r0, r1, addr) \
    asm volatile("ldmatrix.sync.aligned.m8n8.x2.shared.b16 {%0,%1}, [%2];" \
                 : "=r"(r0), "=r"(r1) : "r"(addr))
#define MMA16816(c, a0, a1, a2, a3, b0, b1) \
    asm volatile("mma.sync.aligned.m16n8k16.row.col.f32.bf16.bf16.f32 " \
                 "{%0,%1,%2,%3}, {%4,%5,%6,%7}, {%8,%9}, {%0,%1,%2,%3};" \
                 : "+f"((c)[0]), "+f"((c)[1]), "+f"((c)[2]), "+f"((c)[3]) \
                 : "r"(a0), "r"(a1), "r"(a2), "r"(a3), "r"(b0), "r"(b1))

// ------------------------- split / merge kernels --------------------------
__global__ void split8(const float* __restrict__ in,
                       __nv_bfloat16* __restrict__ hi,
                       __nv_bfloat16* __restrict__ lo) {
    size_t i = ((size_t)blockIdx.x * 256 + threadIdx.x) * 8;
    float v[8];
    *(float4*)&v[0] = *(const float4*)(in + i);
    *(float4*)&v[4] = *(const float4*)(in + i + 4);
    __nv_bfloat16 h[8], l[8];
#pragma unroll
    for (int j = 0; j < 8; j++) {
        h[j] = __float2bfloat16(v[j]);
        l[j] = __float2bfloat16(v[j] - __bfloat162float(h[j]));
    }
    *(float4*)(hi + i) = *(float4*)h;
    *(float4*)(lo + i) = *(float4*)l;
}

__global__ void merge_split(const float* __restrict__ w,
                            const float* __restrict__ a,
                            const float* __restrict__ b,
                            __nv_bfloat16* __restrict__ hi,
                            __nv_bfloat16* __restrict__ lo) {
    int idx = blockIdx.x * 256 + threadIdx.x;
    int n = idx >> 12, k = idx & (D - 1);
    float acc = w[idx];
#pragma unroll
    for (int r = 0; r < LR; r++)
        acc += 2.0f * __ldg(&b[n * LR + r]) * __ldg(&a[r * D + k]);
    __nv_bfloat16 h = __float2bfloat16(acc);
    hi[idx] = h;
    lo[idx] = __float2bfloat16(acc - __bfloat162float(h));
}

// ------------- bf16-split GEMM (NT) on mma.sync tensor cores --------------
// C[m,n] = sum_k A[m,k]*B[n,k], reconstructed as Ah*Bh + Ah*Bl + Al*Bh.
// BM=128, BN=128, BK=32, 256 threads (8 warps, 2x4 M-N grid, 64x32/warp).
// SMEM stage: 4 tiles (Ah,Al,Bh,Bl) of 128 rows x 32 bf16, stride 40 (80B),
// 10240B each -> 40KB/stage, 2 stages = 80KB.
#define GSTAGE  40960
#define GTILE   10240
#define GEMM_SMEM (2 * GSTAGE)

__global__ void __launch_bounds__(256, 1) gemm_mma3(
    const __nv_bfloat16* __restrict__ Ah, const __nv_bfloat16* __restrict__ Al,
    const __nv_bfloat16* __restrict__ Bh, const __nv_bfloat16* __restrict__ Bl,
    float* __restrict__ C) {
    extern __shared__ char smch[];
    const uint32_t smb = smem_to_u32(smch);
    const int tid = threadIdx.x, lane = tid & 31, wid = tid >> 5;
    const int warp_m = wid & 1;          // 0..1 -> 64 rows each
    const int warp_n = wid >> 1;         // 0..3 -> 32 cols each
    const int bm = blockIdx.y * 128, bn = blockIdx.x * 128;

    float acc[4][4][4];
#pragma unroll
    for (int i = 0; i < 4; i++)
#pragma unroll
        for (int j = 0; j < 4; j++)
#pragma unroll
            for (int k = 0; k < 4; k++) acc[i][j][k] = 0.0f;

    // loader: thread covers rows r0, r0+64 at 16B-chunk c4 of each tile
    const int r0 = tid >> 2, c4 = tid & 3;
    const __nv_bfloat16* gA0h = Ah + ((size_t)(bm + r0) << 12) + c4 * 8;
    const __nv_bfloat16* gA0l = Al + ((size_t)(bm + r0) << 12) + c4 * 8;
    const __nv_bfloat16* gB0h = Bh + ((size_t)(bn + r0) << 12) + c4 * 8;
    const __nv_bfloat16* gB0l = Bl + ((size_t)(bn + r0) << 12) + c4 * 8;
    const uint32_t dstoff = r0 * 80 + c4 * 16;

    // ldmatrix source addresses (within a stage/tile)
    const uint32_t a_off = (warp_m * 64 + (lane & 15)) * 80 + ((lane >> 4) << 3) * 2;
    const uint32_t b_off = (warp_n * 32 + (lane & 7)) * 80 + (((lane >> 3) & 1) << 3) * 2;

#define ISSUE(ck, st) do {                                                     \
        uint32_t sb_ = smb + (st) * GSTAGE + dstoff;                           \
        size_t go_ = (size_t)(ck) * 32;                                        \
        CP16(sb_,             (const char*)(gA0h + go_));                      \
        CP16(sb_ + 5120,      (const char*)(gA0h + go_ + ((size_t)64 << 12))); \
        CP16(sb_ + GTILE,     (const char*)(gA0l + go_));                      \
        CP16(sb_ + GTILE+5120,(const char*)(gA0l + go_ + ((size_t)64 << 12))); \
        CP16(sb_ + 2*GTILE,      (const char*)(gB0h + go_));                   \
        CP16(sb_ + 2*GTILE+5120, (const char*)(gB0h + go_ + ((size_t)64<<12)));\
        CP16(sb_ + 3*GTILE,      (const char*)(gB0l + go_));                   \
        CP16(sb_ + 3*GTILE+5120, (const char*)(gB0l + go_ + ((size_t)64<<12)));\
    } while (0)

    ISSUE(0, 0);
    CP_COMMIT();

    for (int ck = 0; ck < 128; ck++) {
        const int st = ck & 1;
        if (ck + 1 < 128) {
            ISSUE(ck + 1, st ^ 1);
            CP_COMMIT();
            CP_WAIT1();
        } else {
            CP_WAIT0();
        }
        __syncthreads();

        const uint32_t sAh = smb + st * GSTAGE;
        const uint32_t sAl = sAh + GTILE;
        const uint32_t sBh = sAh + 2 * GTILE;
        const uint32_t sBl = sAh + 3 * GTILE;

#pragma unroll
        for (int ks = 0; ks < 2; ks++) {
            const uint32_t kb = ks * 32;   // 16 bf16 = 32 bytes
            uint32_t ah[4][4], al[4][4], bh[4][2], bl[4][2];
#pragma unroll
            for (int mt = 0; mt < 4; mt++) {
                uint32_t adr = a_off + mt * 16 * 80 + kb;
                LDSM4(ah[mt][0], ah[mt][1], ah[mt][2], ah[mt][3], sAh + adr);
                LDSM4(al[mt][0], al[mt][1], al[mt][2], al[mt][3], sAl + adr);
            }
#pragma unroll
            for (int nt = 0; nt < 4; nt++) {
                uint32_t adr = b_off + nt * 8 * 80 + kb;
                LDSM2(bh[nt][0], bh[nt][1], sBh + adr);
                LDSM2(bl[nt][0], bl[nt][1], sBl + adr);
            }
#pragma unroll
            for (int mt = 0; mt < 4; mt++)
#pragma unroll
                for (int nt = 0; nt < 4; nt++) {
                    MMA16816(acc[mt][nt], ah[mt][0], ah[mt][1], ah[mt][2], ah[mt][3],
                             bh[nt][0], bh[nt][1]);
                    MMA16816(acc[mt][nt], ah[mt][0], ah[mt][1], ah[mt][2], ah[mt][3],
                             bl[nt][0], bl[nt][1]);
                    MMA16816(acc[mt][nt], al[mt][0], al[mt][1], al[mt][2], al[mt][3],
                             bh[nt][0], bh[nt][1]);
                }
        }
        __syncthreads();
    }

    // epilogue
#pragma unroll
    for (int mt = 0; mt < 4; mt++) {
        const int row = bm + warp_m * 64 + mt * 16 + (lane >> 2);
#pragma unroll
        for (int nt = 0; nt < 4; nt++) {
            const int col = bn + warp_n * 32 + nt * 8 + (lane & 3) * 2;
            *(float2*)&C[(size_t)row * D + col] =
                make_float2(acc[mt][nt][0], acc[mt][nt][1]);
            *(float2*)&C[(size_t)(row + 8) * D + col] =
                make_float2(acc[mt][nt][2], acc[mt][nt][3]);
        }
    }
}

// ---------------- RoPE on g_Q and g_K (in place) ---------------------------
__global__ void rope_kernel(const float* __restrict__ fc,
                            const float* __restrict__ fs) {
    int p = blockIdx.x * 256 + threadIdx.x;
    int row = p >> 11;
    int cp  = p & 2047;
    int i   = cp & 63;
    int s   = row & (SEQ - 1);
    float c  = fc[s * 64 + i];
    float sn = fs[s * 64 + i];
    size_t base = (size_t)row * D + cp * 2;
    float2 q = *(float2*)&g_Q[base];
    *(float2*)&g_Q[base] = make_float2(q.x * c - q.y * sn, q.x * sn + q.y * c);
    float2 k = *(float2*)&g_K[base];
    *(float2*)&g_K[base] = make_float2(k.x * c - k.y * sn, k.x * sn + k.y * c);
}

// ---------------- flash attention (fp32, causal) ---------------------------
#define ATTN_SMEM ((128 * 132 + 64 * 132 + 64 * 132 + 128 * 68) * 4)

__global__ void __launch_bounds__(256) attn_kernel() {
    extern __shared__ float smf[];
    float* Qs = smf;
    float* Ks = smf + 128 * 132;
    float* Vs = Ks + 64 * 132;
    float* Ps = Vs + 64 * 132;

    const int b = blockIdx.z, h = blockIdx.y, qt = blockIdx.x;
    const int q0 = qt * 128;
    const int tid = threadIdx.x;
    const int tx = tid & 7, ty = tid >> 3;
    const float SCALE = 0.08838834764831845f;

    const float* Qg = g_Q + ((size_t)(b * SEQ + q0)) * D + h * HD;
    const float* Kg = g_K + ((size_t)(b * SEQ)) * D + h * HD;
    const float* Vg = g_V + ((size_t)(b * SEQ)) * D + h * HD;

    for (int l = tid; l < 128 * 32; l += 256) {
        int row = l >> 5, c4 = l & 31;
        *(float4*)&Qs[row * 132 + c4 * 4] = *(const float4*)&Qg[(size_t)row * D + c4 * 4];
    }

    float o[4][16];
    float m[4], lsum[4];
#pragma unroll
    for (int r = 0; r < 4; r++) {
        m[r] = -1e30f; lsum[r] = 0.0f;
#pragma unroll
        for (int c = 0; c < 16; c++) o[r][c] = 0.0f;
    }

    const int ktiles = 2 * qt + 2;
    for (int kt = 0; kt < ktiles; kt++) {
        const int k0 = kt * 64;
        __syncthreads();
        for (int l = tid; l < 64 * 32; l += 256) {
            int row = l >> 5, c4 = l & 31;
            *(float4*)&Ks[row * 132 + c4 * 4] = *(const float4*)&Kg[(size_t)(k0 + row) * D + c4 * 4];
            *(float4*)&Vs[row * 132 + c4 * 4] = *(const float4*)&Vg[(size_t)(k0 + row) * D + c4 * 4];
        }
        __syncthreads();

        float sc[4][8];
#pragma unroll
        for (int r = 0; r < 4; r++)
#pragma unroll
            for (int c = 0; c < 8; c++) sc[r][c] = 0.0f;

#pragma unroll 4
        for (int kk4 = 0; kk4 < 32; kk4++) {
            float4 a4[4], b4[8];
#pragma unroll
            for (int r = 0; r < 4; r++)
                a4[r] = *(const float4*)&Qs[(ty * 4 + r) * 132 + kk4 * 4];
#pragma unroll
            for (int c = 0; c < 8; c++)
                b4[c] = *(const float4*)&Ks[(tx + 8 * c) * 132 + kk4 * 4];
#pragma unroll
            for (int r = 0; r < 4; r++)
#pragma unroll
                for (int c = 0; c < 8; c++)
                    sc[r][c] += a4[r].x * b4[c].x + a4[r].y * b4[c].y +
                                a4[r].z * b4[c].z + a4[r].w * b4[c].w;
        }

        const bool need_mask = (k0 + 63 > q0);
#pragma unroll
        for (int r = 0; r < 4; r++) {
            int ig = q0 + ty * 4 + r;
#pragma unroll
            for (int c = 0; c < 8; c++) {
                float v = sc[r][c] * SCALE;
                if (need_mask && (k0 + tx + 8 * c > ig)) v = -1e30f;
                sc[r][c] = v;
            }
        }

#pragma unroll
        for (int r = 0; r < 4; r++) {
            float mx = sc[r][0];
#pragma unroll
            for (int c = 1; c < 8; c++) mx = fmaxf(mx, sc[r][c]);
            mx = fmaxf(mx, __shfl_xor_sync(0xffffffffu, mx, 1));
            mx = fmaxf(mx, __shfl_xor_sync(0xffffffffu, mx, 2));
            mx = fmaxf(mx, __shfl_xor_sync(0xffffffffu, mx, 4));
            float mnew = fmaxf(m[r], mx);
            float alpha = __expf(m[r] - mnew);
            float s = 0.0f;
#pragma unroll
            for (int c = 0; c < 8; c++) {
                float p = __expf(sc[r][c] - mnew);
                sc[r][c] = p;
                s += p;
            }
            s += __shfl_xor_sync(0xffffffffu, s, 1);
            s += __shfl_xor_sync(0xffffffffu, s, 2);
            s += __shfl_xor_sync(0xffffffffu, s, 4);
            lsum[r] = lsum[r] * alpha + s;
            m[r] = mnew;
#pragma unroll
            for (int c = 0; c < 16; c++) o[r][c] *= alpha;
        }

#pragma unroll
        for (int r = 0; r < 4; r++)
#pragma unroll
            for (int c = 0; c < 8; c++)
                Ps[(ty * 4 + r) * 68 + tx + 8 * c] = sc[r][c];
        __syncthreads();

#pragma unroll 2
        for (int j = 0; j < 64; j++) {
            float p[4];
#pragma unroll
            for (int r = 0; r < 4; r++) p[r] = Ps[(ty * 4 + r) * 68 + j];
#pragma unroll
            for (int c = 0; c < 16; c++) {
                float v = Vs[j * 132 + tx + 8 * c];
#pragma unroll
                for (int r = 0; r < 4; r++) o[r][c] += p[r] * v;
            }
        }
    }

#pragma unroll
    for (int r = 0; r < 4; r++) {
        float inv = 1.0f / lsum[r];
        size_t rowoff = ((size_t)(b * SEQ + q0 + ty * 4 + r)) * D + h * HD;
#pragma unroll
        for (int c = 0; c < 16; c++)
            g_O[rowoff + tx + 8 * c] = o[r][c] * inv;
    }
}

// ---------------- launcher -------------------------------------------------
extern "C" void kernel_launch(void* const* d_in, const int* in_sizes, int n_in,
                              void* d_out, int out_size) {
    const float* x    = (const float*)d_in[0];
    const float* wq_w = (const float*)d_in[1];
    const float* wq_a = (const float*)d_in[2];
    const float* wq_b = (const float*)d_in[3];
    const float* wk_w = (const float*)d_in[4];
    const float* wv_w = (const float*)d_in[5];
    const float* wv_a = (const float*)d_in[6];
    const float* wv_b = (const float*)d_in[7];
    const float* wo_w = (const float*)d_in[8];
    const float* fc   = (const float*)d_in[9];
    const float* fs   = (const float*)d_in[10];
    float* out = (float*)d_out;

    __nv_bfloat16 *xh, *xl, *Wqh, *Wql, *Wkh, *Wkl, *Wvh, *Wvl, *Woh, *Wol, *Oh, *Ol;
    float *Q, *K, *V, *O;
    cudaGetSymbolAddress((void**)&xh, g_xh);   cudaGetSymbolAddress((void**)&xl, g_xl);
    cudaGetSymbolAddress((void**)&Wqh, g_Wqh); cudaGetSymbolAddress((void**)&Wql, g_Wql);
    cudaGetSymbolAddress((void**)&Wkh, g_Wkh); cudaGetSymbolAddress((void**)&Wkl, g_Wkl);
    cudaGetSymbolAddress((void**)&Wvh, g_Wvh); cudaGetSymbolAddress((void**)&Wvl, g_Wvl);
    cudaGetSymbolAddress((void**)&Woh, g_Woh); cudaGetSymbolAddress((void**)&Wol, g_Wol);
    cudaGetSymbolAddress((void**)&Oh, g_Oh);   cudaGetSymbolAddress((void**)&Ol, g_Ol);
    cudaGetSymbolAddress((void**)&Q, g_Q);     cudaGetSymbolAddress((void**)&K, g_K);
    cudaGetSymbolAddress((void**)&V, g_V);     cudaGetSymbolAddress((void**)&O, g_O);

    cudaFuncSetAttribute(gemm_mma3,
                         cudaFuncAttributeMaxDynamicSharedMemorySize, GEMM_SMEM);
    cudaFuncSetAttribute(attn_kernel,
                         cudaFuncAttributeMaxDynamicSharedMemorySize, ATTN_SMEM);

    // 1) fold LoRA + split to bf16 hi/lo
    merge_split<<<(D * D) / 256, 256>>>(wq_w, wq_a, wq_b, Wqh, Wql);
    merge_split<<<(D * D) / 256, 256>>>(wv_w, wv_a, wv_b, Wvh, Wvl);
    split8<<<(D * D) / 8 / 256, 256>>>(wk_w, Wkh, Wkl);
    split8<<<(D * D) / 8 / 256, 256>>>(wo_w, Woh, Wol);
    split8<<<((size_t)BSR * D) / 8 / 256, 256>>>(x, xh, xl);

    // 2) projections on tensor cores (mma.sync bf16 x3)
    dim3 g(D / 128, BSR / 128);  // (32, 32)
    gemm_mma3<<<g, 256, GEMM_SMEM>>>(xh, xl, Wqh, Wql, Q);
    gemm_mma3<<<g, 256, GEMM_SMEM>>>(xh, xl, Wkh, Wkl, K);
    gemm_mma3<<<g, 256, GEMM_SMEM>>>(xh, xl, Wvh, Wvl, V);

    // 3) RoPE
    rope_kernel<<<(BSR * (D / 2)) / 256, 256>>>(fc, fs);

    // 4) causal flash attention -> g_O
    attn_kernel<<<dim3(SEQ / 128, NH, 4), 256, ATTN_SMEM>>>();

    // 5) output projection
    split8<<<((size_t)BSR * D) / 8 / 256, 256>>>(O, Oh, Ol);
    gemm_mma3<<<g, 256, GEMM_SMEM>>>(Oh, Ol, Woh, Wol, out);
}

// round 4
// speedup vs baseline: 2.5792x; 1.2485x over previous
#include <cuda_runtime.h>
#include <cuda_bf16.h>
#include <cstdint>

#define D   4096
#define BSR 4096
#define SEQ 1024
#define NH  32
#define HD  128
#define LR  16

// ------------------------- device scratch ---------------------------------
__device__ __nv_bfloat16 g_xh[(size_t)BSR * D], g_xl[(size_t)BSR * D];
__device__ __nv_bfloat16 g_Wqh[(size_t)D * D], g_Wql[(size_t)D * D];
__device__ __nv_bfloat16 g_Wkh[(size_t)D * D], g_Wkl[(size_t)D * D];
__device__ __nv_bfloat16 g_Wvh[(size_t)D * D], g_Wvl[(size_t)D * D];
__device__ __nv_bfloat16 g_Woh[(size_t)D * D], g_Wol[(size_t)D * D];
__device__ __nv_bfloat16 g_Oh[(size_t)BSR * D], g_Ol[(size_t)BSR * D];
__device__ float g_Q[(size_t)BSR * D], g_K[(size_t)BSR * D];
__device__ float g_V[(size_t)BSR * D];

// ------------------------- PTX helpers (base-target only) ------------------
__device__ __forceinline__ uint32_t smem_to_u32(const void* p) {
    uint32_t a;
    asm("{ .reg .u64 t; cvta.to.shared.u64 t, %1; cvt.u32.u64 %0, t; }"
        : "=r"(a) : "l"(p));
    return a;
}
#define CP16(dst, src) \
    asm volatile("cp.async.cg.shared.global [%0], [%1], 16;" \
                 :: "r"(dst), "l"(src))
#define CP_COMMIT() asm volatile("cp.async.commit_group;" ::: "memory")
#define CP_WAIT1()  asm volatile("cp.async.wait_group 1;" ::: "memory")
#define CP_WAIT0()  asm volatile("cp.async.wait_group 0;" ::: "memory")

#define LDSM4(r0, r1, r2, r3, addr) \
    asm volatile("ldmatrix.sync.aligned.m8n8.x4.shared.b16 {%0,%1,%2,%3}, [%4];" \
                 : "=r"(r0), "=r"(r1), "=r"(r2), "=r"(r3) : "r"(addr))
#define LDSM2(r0, r1, addr) \
    asm volatile("ldmatrix.sync.aligned.m8n8.x2.shared.b16 {%0,%1}, [%2];" \
                 : "=r"(r0), "=r"(r1) : "r"(addr))
#define MMA16816(c, a0, a1, a2, a3, b0, b1) \
    asm volatile("mma.sync.aligned.m16n8k16.row.col.f32.bf16.bf16.f32 " \
                 "{%0,%1,%2,%3}, {%4,%5,%6,%7}, {%8,%9}, {%0,%1,%2,%3};" \
                 : "+f"((c)[0]), "+f"((c)[1]), "+f"((c)[2]), "+f"((c)[3]) \
                 : "r"(a0), "r"(a1), "r"(a2), "r"(a3), "r"(b0), "r"(b1))

// ------------------------- split / merge kernels --------------------------
__global__ void split8(const float* __restrict__ in,
                       __nv_bfloat16* __restrict__ hi,
                       __nv_bfloat16* __restrict__ lo) {
    size_t i = ((size_t)blockIdx.x * 256 + threadIdx.x) * 8;
    float v[8];
    *(float4*)&v[0] = *(const float4*)(in + i);
    *(float4*)&v[4] = *(const float4*)(in + i + 4);
    __nv_bfloat16 h[8], l[8];
#pragma unroll
    for (int j = 0; j < 8; j++) {
        h[j] = __float2bfloat16(v[j]);
        l[j] = __float2bfloat16(v[j] - __bfloat162float(h[j]));
    }
    *(float4*)(hi + i) = *(float4*)h;
    *(float4*)(lo + i) = *(float4*)l;
}

__global__ void merge_split(const float* __restrict__ w,
                            const float* __restrict__ a,
                            const float* __restrict__ b,
                            __nv_bfloat16* __restrict__ hi,
                            __nv_bfloat16* __restrict__ lo) {
    int idx = blockIdx.x * 256 + threadIdx.x;
    int n = idx >> 12, k = idx & (D - 1);
    float acc = w[idx];
#pragma unroll
    for (int r = 0; r < LR; r++)
        acc += 2.0f * __ldg(&b[n * LR + r]) * __ldg(&a[r * D + k]);
    __nv_bfloat16 h = __float2bfloat16(acc);
    hi[idx] = h;
    lo[idx] = __float2bfloat16(acc - __bfloat162float(h));
}

// ------------- bf16-split GEMM (NT) on mma.sync tensor cores --------------
// C = Ah*Bh^T + Ah*Bl^T + Al*Bh^T.  BM=BN=128, BK=64, 256 thr (8 warps 2x4).
// SMEM: 3 stages x 4 tiles (Ah,Al,Bh,Bl), tile = 128 rows x 128B, XOR-swizzled.
#define GTILE   16384
#define GSTAGE  (4 * GTILE)
#define NSTAGE  3
#define GEMM_SMEM (NSTAGE * GSTAGE)

__global__ void __launch_bounds__(256, 1) gemm_mma3(
    const __nv_bfloat16* __restrict__ Ah, const __nv_bfloat16* __restrict__ Al,
    const __nv_bfloat16* __restrict__ Bh, const __nv_bfloat16* __restrict__ Bl,
    float* __restrict__ C) {
    extern __shared__ char smch[];
    const uint32_t smb = smem_to_u32(smch);
    const int tid = threadIdx.x, lane = tid & 31, wid = tid >> 5;
    const int warp_m = wid & 1;          // 64 rows each
    const int warp_n = wid >> 1;         // 32 cols each
    const int bm = blockIdx.y * 128, bn = blockIdx.x * 128;

    float acc[4][4][4];
#pragma unroll
    for (int i = 0; i < 4; i++)
#pragma unroll
        for (int j = 0; j < 4; j++)
#pragma unroll
            for (int k = 0; k < 4; k++) acc[i][j][k] = 0.0f;

    // loader mapping: thread -> (row0 = tid/8, chunk c0 = tid%8), 4 row-groups
    const int r0 = tid >> 3, c0 = tid & 7;
    const uint32_t dst0 = r0 * 128 + (uint32_t)((c0 ^ (r0 & 7)) * 16);
    const __nv_bfloat16* gAh = Ah + ((size_t)(bm + r0) << 12) + c0 * 8;
    const __nv_bfloat16* gAl = Al + ((size_t)(bm + r0) << 12) + c0 * 8;
    const __nv_bfloat16* gBh = Bh + ((size_t)(bn + r0) << 12) + c0 * 8;
    const __nv_bfloat16* gBl = Bl + ((size_t)(bn + r0) << 12) + c0 * 8;

#define ISSUE(ck, st) do {                                                     \
        const uint32_t sb_ = smb + (st) * GSTAGE + dst0;                       \
        const size_t go_ = (size_t)(ck) * 64;                                  \
        _Pragma("unroll")                                                      \
        for (int j = 0; j < 4; j++) {                                          \
            const uint32_t d_ = sb_ + j * 32 * 128;                            \
            const size_t s_ = go_ + ((size_t)j << 17);  /* 32 rows * 4096 */   \
            CP16(d_,             (const char*)(gAh + s_));                     \
            CP16(d_ + GTILE,     (const char*)(gAl + s_));                     \
            CP16(d_ + 2 * GTILE, (const char*)(gBh + s_));                     \
            CP16(d_ + 3 * GTILE, (const char*)(gBl + s_));                     \
        }                                                                      \
        CP_COMMIT();                                                           \
    } while (0)

    ISSUE(0, 0);
    ISSUE(1, 1);

    // ldmatrix per-lane bases
    const int arow = warp_m * 64 + (lane & 15);        // + mt*16
    const int akh  = lane >> 4;                         // k half
    const int brow = warp_n * 32 + (lane & 7);          // + nt*8
    const int bkh  = (lane >> 3) & 1;

    for (int ck = 0; ck < 64; ck++) {
        const int st = ck % NSTAGE;
        CP_WAIT1();
        __syncthreads();
        if (ck + 2 < 64) ISSUE(ck + 2, (ck + 2) % NSTAGE);

        const uint32_t sAh = smb + st * GSTAGE;
        const uint32_t sAl = sAh + GTILE;
        const uint32_t sBh = sAh + 2 * GTILE;
        const uint32_t sBl = sAh + 3 * GTILE;

#pragma unroll
        for (int ks = 0; ks < 4; ks++) {
            uint32_t ah[4][4], al[4][4], bh[4][2], bl[4][2];
#pragma unroll
            for (int mt = 0; mt < 4; mt++) {
                const int r = arow + mt * 16;
                const uint32_t adr = r * 128 + (((ks * 2 + akh) ^ (r & 7)) * 16);
                LDSM4(ah[mt][0], ah[mt][1], ah[mt][2], ah[mt][3], sAh + adr);
                LDSM4(al[mt][0], al[mt][1], al[mt][2], al[mt][3], sAl + adr);
            }
#pragma unroll
            for (int nt = 0; nt < 4; nt++) {
                const int r = brow + nt * 8;
                const uint32_t adr = r * 128 + (((ks * 2 + bkh) ^ (r & 7)) * 16);
                LDSM2(bh[nt][0], bh[nt][1], sBh + adr);
                LDSM2(bl[nt][0], bl[nt][1], sBl + adr);
            }
#pragma unroll
            for (int mt = 0; mt < 4; mt++)
#pragma unroll
                for (int nt = 0; nt < 4; nt++) {
                    MMA16816(acc[mt][nt], ah[mt][0], ah[mt][1], ah[mt][2], ah[mt][3],
                             bh[nt][0], bh[nt][1]);
                    MMA16816(acc[mt][nt], ah[mt][0], ah[mt][1], ah[mt][2], ah[mt][3],
                             bl[nt][0], bl[nt][1]);
                    MMA16816(acc[mt][nt], al[mt][0], al[mt][1], al[mt][2], al[mt][3],
                             bh[nt][0], bh[nt][1]);
                }
        }
        __syncthreads();
    }

    // epilogue
#pragma unroll
    for (int mt = 0; mt < 4; mt++) {
        const int row = bm + warp_m * 64 + mt * 16 + (lane >> 2);
#pragma unroll
        for (int nt = 0; nt < 4; nt++) {
            const int col = bn + warp_n * 32 + nt * 8 + (lane & 3) * 2;
            *(float2*)&C[(size_t)row * D + col] =
                make_float2(acc[mt][nt][0], acc[mt][nt][1]);
            *(float2*)&C[(size_t)(row + 8) * D + col] =
                make_float2(acc[mt][nt][2], acc[mt][nt][3]);
        }
    }
}

// ---------------- RoPE on g_Q and g_K (in place) ---------------------------
__global__ void rope_kernel(const float* __restrict__ fc,
                            const float* __restrict__ fs) {
    int p = blockIdx.x * 256 + threadIdx.x;
    int row = p >> 11;
    int cp  = p & 2047;
    int i   = cp & 63;
    int s   = row & (SEQ - 1);
    float c  = fc[s * 64 + i];
    float sn = fs[s * 64 + i];
    size_t base = (size_t)row * D + cp * 2;
    float2 q = *(float2*)&g_Q[base];
    *(float2*)&g_Q[base] = make_float2(q.x * c - q.y * sn, q.x * sn + q.y * c);
    float2 k = *(float2*)&g_K[base];
    *(float2*)&g_K[base] = make_float2(k.x * c - k.y * sn, k.x * sn + k.y * c);
}

// ---------------- flash attention (fp32, causal) ---------------------------
// epilogue writes bf16 hi/lo directly (feeds O-projection GEMM).
#define ATTN_SMEM ((128 * 132 + 64 * 132 + 64 * 132 + 128 * 68) * 4)

__global__ void __launch_bounds__(256) attn_kernel() {
    extern __shared__ float smf[];
    float* Qs = smf;
    float* Ks = smf + 128 * 132;
    float* Vs = Ks + 64 * 132;
    float* Ps = Vs + 64 * 132;

    const int b = blockIdx.z, h = blockIdx.y, qt = blockIdx.x;
    const int q0 = qt * 128;
    const int tid = threadIdx.x;
    const int tx = tid & 7, ty = tid >> 3;
    const float SCALE = 0.08838834764831845f;

    const float* Qg = g_Q + ((size_t)(b * SEQ + q0)) * D + h * HD;
    const float* Kg = g_K + ((size_t)(b * SEQ)) * D + h * HD;
    const float* Vg = g_V + ((size_t)(b * SEQ)) * D + h * HD;

    for (int l = tid; l < 128 * 32; l += 256) {
        int row = l >> 5, c4 = l & 31;
        *(float4*)&Qs[row * 132 + c4 * 4] = *(const float4*)&Qg[(size_t)row * D + c4 * 4];
    }

    float o[4][16];
    float m[4], lsum[4];
#pragma unroll
    for (int r = 0; r < 4; r++) {
        m[r] = -1e30f; lsum[r] = 0.0f;
#pragma unroll
        for (int c = 0; c < 16; c++) o[r][c] = 0.0f;
    }

    const int ktiles = 2 * qt + 2;
    for (int kt = 0; kt < ktiles; kt++) {
        const int k0 = kt * 64;
        __syncthreads();
        for (int l = tid; l < 64 * 32; l += 256) {
            int row = l >> 5, c4 = l & 31;
            *(float4*)&Ks[row * 132 + c4 * 4] = *(const float4*)&Kg[(size_t)(k0 + row) * D + c4 * 4];
            *(float4*)&Vs[row * 132 + c4 * 4] = *(const float4*)&Vg[(size_t)(k0 + row) * D + c4 * 4];
        }
        __syncthreads();

        float sc[4][8];
#pragma unroll
        for (int r = 0; r < 4; r++)
#pragma unroll
            for (int c = 0; c < 8; c++) sc[r][c] = 0.0f;

#pragma unroll 4
        for (int kk4 = 0; kk4 < 32; kk4++) {
            float4 a4[4], b4[8];
#pragma unroll
            for (int r = 0; r < 4; r++)
                a4[r] = *(const float4*)&Qs[(ty * 4 + r) * 132 + kk4 * 4];
#pragma unroll
            for (int c = 0; c < 8; c++)
                b4[c] = *(const float4*)&Ks[(tx + 8 * c) * 132 + kk4 * 4];
#pragma unroll
            for (int r = 0; r < 4; r++)
#pragma unroll
                for (int c = 0; c < 8; c++)
                    sc[r][c] += a4[r].x * b4[c].x + a4[r].y * b4[c].y +
                                a4[r].z * b4[c].z + a4[r].w * b4[c].w;
        }

        const bool need_mask = (k0 + 63 > q0);
#pragma unroll
        for (int r = 0; r < 4; r++) {
            int ig = q0 + ty * 4 + r;
#pragma unroll
            for (int c = 0; c < 8; c++) {
                float v = sc[r][c] * SCALE;
                if (need_mask && (k0 + tx + 8 * c > ig)) v = -1e30f;
                sc[r][c] = v;
            }
        }

#pragma unroll
        for (int r = 0; r < 4; r++) {
            float mx = sc[r][0];
#pragma unroll
            for (int c = 1; c < 8; c++) mx = fmaxf(mx, sc[r][c]);
            mx = fmaxf(mx, __shfl_xor_sync(0xffffffffu, mx, 1));
            mx = fmaxf(mx, __shfl_xor_sync(0xffffffffu, mx, 2));
            mx = fmaxf(mx, __shfl_xor_sync(0xffffffffu, mx, 4));
            float mnew = fmaxf(m[r], mx);
            float alpha = __expf(m[r] - mnew);
            float s = 0.0f;
#pragma unroll
            for (int c = 0; c < 8; c++) {
                float p = __expf(sc[r][c] - mnew);
                sc[r][c] = p;
                s += p;
            }
            s += __shfl_xor_sync(0xffffffffu, s, 1);
            s += __shfl_xor_sync(0xffffffffu, s, 2);
            s += __shfl_xor_sync(0xffffffffu, s, 4);
            lsum[r] = lsum[r] * alpha + s;
            m[r] = mnew;
#pragma unroll
            for (int c = 0; c < 16; c++) o[r][c] *= alpha;
        }

#pragma unroll
        for (int r = 0; r < 4; r++)
#pragma unroll
            for (int c = 0; c < 8; c++)
                Ps[(ty * 4 + r) * 68 + tx + 8 * c] = sc[r][c];
        __syncthreads();

#pragma unroll 2
        for (int j = 0; j < 64; j++) {
            float p[4];
#pragma unroll
            for (int r = 0; r < 4; r++) p[r] = Ps[(ty * 4 + r) * 68 + j];
#pragma unroll
            for (int c = 0; c < 16; c++) {
                float v = Vs[j * 132 + tx + 8 * c];
#pragma unroll
                for (int r = 0; r < 4; r++) o[r][c] += p[r] * v;
            }
        }
    }

    // epilogue: normalize + split to bf16 hi/lo directly
#pragma unroll
    for (int r = 0; r < 4; r++) {
        float inv = 1.0f / lsum[r];
        size_t rowoff = ((size_t)(b * SEQ + q0 + ty * 4 + r)) * D + h * HD;
#pragma unroll
        for (int c = 0; c < 16; c++) {
            float val = o[r][c] * inv;
            __nv_bfloat16 hh = __float2bfloat16(val);
            g_Oh[rowoff + tx + 8 * c] = hh;
            g_Ol[rowoff + tx + 8 * c] = __float2bfloat16(val - __bfloat162float(hh));
        }
    }
}

// ---------------- launcher -------------------------------------------------
extern "C" void kernel_launch(void* const* d_in, const int* in_sizes, int n_in,
                              void* d_out, int out_size) {
    const float* x    = (const float*)d_in[0];
    const float* wq_w = (const float*)d_in[1];
    const float* wq_a = (const float*)d_in[2];
    const float* wq_b = (const float*)d_in[3];
    const float* wk_w = (const float*)d_in[4];
    const float* wv_w = (const float*)d_in[5];
    const float* wv_a = (const float*)d_in[6];
    const float* wv_b = (const float*)d_in[7];
    const float* wo_w = (const float*)d_in[8];
    const float* fc   = (const float*)d_in[9];
    const float* fs   = (const float*)d_in[10];
    float* out = (float*)d_out;

    __nv_bfloat16 *xh, *xl, *Wqh, *Wql, *Wkh, *Wkl, *Wvh, *Wvl, *Woh, *Wol, *Oh, *Ol;
    float *Q, *K, *V;
    cudaGetSymbolAddress((void**)&xh, g_xh);   cudaGetSymbolAddress((void**)&xl, g_xl);
    cudaGetSymbolAddress((void**)&Wqh, g_Wqh); cudaGetSymbolAddress((void**)&Wql, g_Wql);
    cudaGetSymbolAddress((void**)&Wkh, g_Wkh); cudaGetSymbolAddress((void**)&Wkl, g_Wkl);
    cudaGetSymbolAddress((void**)&Wvh, g_Wvh); cudaGetSymbolAddress((void**)&Wvl, g_Wvl);
    cudaGetSymbolAddress((void**)&Woh, g_Woh); cudaGetSymbolAddress((void**)&Wol, g_Wol);
    cudaGetSymbolAddress((void**)&Oh, g_Oh);   cudaGetSymbolAddress((void**)&Ol, g_Ol);
    cudaGetSymbolAddress((void**)&Q, g_Q);     cudaGetSymbolAddress((void**)&K, g_K);
    cudaGetSymbolAddress((void**)&V, g_V);

    cudaFuncSetAttribute(gemm_mma3,
                         cudaFuncAttributeMaxDynamicSharedMemorySize, GEMM_SMEM);
    cudaFuncSetAttribute(attn_kernel,
                         cudaFuncAttributeMaxDynamicSharedMemorySize, ATTN_SMEM);

    // 1) fold LoRA + split to bf16 hi/lo
    merge_split<<<(D * D) / 256, 256>>>(wq_w, wq_a, wq_b, Wqh, Wql);
    merge_split<<<(D * D) / 256, 256>>>(wv_w, wv_a, wv_b, Wvh, Wvl);
    split8<<<(D * D) / 8 / 256, 256>>>(wk_w, Wkh, Wkl);
    split8<<<(D * D) / 8 / 256, 256>>>(wo_w, Woh, Wol);
    split8<<<((size_t)BSR * D) / 8 / 256, 256>>>(x, xh, xl);

    // 2) projections on tensor cores (mma.sync bf16 x3)
    dim3 g(D / 128, BSR / 128);  // (32, 32)
    gemm_mma3<<<g, 256, GEMM_SMEM>>>(xh, xl, Wqh, Wql, Q);
    gemm_mma3<<<g, 256, GEMM_SMEM>>>(xh, xl, Wkh, Wkl, K);
    gemm_mma3<<<g, 256, GEMM_SMEM>>>(xh, xl, Wvh, Wvl, V);

    // 3) RoPE
    rope_kernel<<<(BSR * (D / 2)) / 256, 256>>>(fc, fs);

    // 4) causal flash attention -> g_Oh/g_Ol (bf16 split fused in epilogue)
    attn_kernel<<<dim3(SEQ / 128, NH, 4), 256, ATTN_SMEM>>>();

    // 5) output projection
    gemm_mma3<<<g, 256, GEMM_SMEM>>>(Oh, Ol, Woh, Wol, out);
}